// round 12
// baseline (speedup 1.0000x reference)
#include <cuda_runtime.h>
#include <cuda_fp16.h>
#include <cstdint>
#include <math.h>

// out = GELU_exact(x @ W.T + b)
// R12: fp16 single-term mma.sync GEMM.
//  - A path: NO smem/ldmatrix/pack. Each lane LDG.64s its own m16n8k16 fragment
//    elements straight from f32 x and packs with F2FP (rne) in registers.
//  - B path: W pre-packed to f16 (tiny kernel), cp.async 3-stage ring + ldmatrix.
//  - Tile 128x128, 8 warps (warp 64x32), occ 2, grid (64,4).

#define NN 8192
#define KK 512
#define OO 512

#define BM 128
#define BN 128
#define BK 64                    // k per tile (f16: 128 B/row)
#define NKT (KK / BK)            // 8
#define THREADS 256

#define STAGE  16384             // B only: 128 rows x 128 B
#define NSTAGE 3
#define SMEM_TOTAL (NSTAGE * STAGE)   // 48 KB

__device__ __align__(128) __half g_wh[OO * KK];   // 0.5 MB packed W

__device__ __forceinline__ uint32_t smem_u32(const void* p) {
    uint32_t a;
    asm("{ .reg .u64 t; cvta.to.shared.u64 t, %1; cvt.u32.u64 %0, t; }" : "=r"(a) : "l"(p));
    return a;
}

#define CP16(dst, src) \
    asm volatile("cp.async.cg.shared.global [%0], [%1], 16;" :: "r"(dst), "l"(src) : "memory")
#define CP_COMMIT() asm volatile("cp.async.commit_group;" ::: "memory")
#define CP_WAIT1()  asm volatile("cp.async.wait_group 1;" ::: "memory")

__device__ __forceinline__ void ldm4(uint32_t* r, uint32_t addr) {
    asm volatile("ldmatrix.sync.aligned.m8n8.x4.shared.b16 {%0,%1,%2,%3}, [%4];"
                 : "=r"(r[0]), "=r"(r[1]), "=r"(r[2]), "=r"(r[3]) : "r"(addr));
}

__device__ __forceinline__ void mma_f16(float* d, const uint32_t* a, const uint32_t* b) {
    asm volatile(
        "mma.sync.aligned.m16n8k16.row.col.f32.f16.f16.f32 "
        "{%0,%1,%2,%3}, {%4,%5,%6,%7}, {%8,%9}, {%0,%1,%2,%3};"
        : "+f"(d[0]), "+f"(d[1]), "+f"(d[2]), "+f"(d[3])
        : "r"(a[0]), "r"(a[1]), "r"(a[2]), "r"(a[3]), "r"(b[0]), "r"(b[1]));
}

__device__ __forceinline__ uint32_t packh2(float2 u) {
    __half2 h = __float22half2_rn(u);
    return *(uint32_t*)&h;
}

// swizzled byte offset in a 128B-row tile: row r, 16B-chunk c (0..7)
__device__ __forceinline__ uint32_t swz8(int r, int c) {
    return (uint32_t)(r * 128 + (((c ^ (r & 7))) << 4));
}

// A&S 7.1.26 erf (abs err 1.5e-7)
__device__ __forceinline__ float gelu_f(float h) {
    float s = h * 0.70710678118654752f;
    float a = fabsf(s);
    float t = __frcp_rn(fmaf(0.3275911f, a, 1.0f));
    float p = fmaf(fmaf(fmaf(fmaf(1.061405429f, t, -1.453152027f), t, 1.421413741f),
                        t, -0.284496736f), t, 0.254829592f) * t;
    float e = __expf(-a * a);
    float erfv = fmaf(-p, e, 1.0f);
    erfv = copysignf(erfv, s);
    return 0.5f * h * (1.0f + erfv);
}

// ---------------- W pack kernel: f32 -> fp16 (rne), 0.5 MB ----------------
__global__ __launch_bounds__(256) void packw_kernel(const float* __restrict__ W) {
    const int g = blockIdx.x * 256 + threadIdx.x;   // 32768 groups of 8
    const float* src = W + (size_t)g * 8;
    __half* dst = g_wh + (size_t)g * 8;
    float4 v0 = *(const float4*)src;
    float4 v1 = *(const float4*)(src + 4);
    uint32_t o[4];
    o[0] = packh2(make_float2(v0.x, v0.y));
    o[1] = packh2(make_float2(v0.z, v0.w));
    o[2] = packh2(make_float2(v1.x, v1.y));
    o[3] = packh2(make_float2(v1.z, v1.w));
    *(uint4*)dst = make_uint4(o[0], o[1], o[2], o[3]);
}

// ---------------- main GEMM kernel ----------------
__global__ __launch_bounds__(THREADS, 2)
void gemm_f16_kernel(const float* __restrict__ x, const float* __restrict__ bias,
                     float* __restrict__ C) {
    extern __shared__ uint8_t smem[];
    const uint32_t S = smem_u32(smem);
    const int tid = threadIdx.x;
    const int l = tid & 31, wid = tid >> 5;
    const int mwarp = wid & 1;   // 2 M-warps of 64 rows
    const int nwarp = wid >> 1;  // 4 N-warps of 32 cols
    const int mb = blockIdx.x, nb = blockIdx.y;

    // ---- B loader (cp.async, 4 chunks/thread/kt), hoisted ----
    const int lr0 = tid >> 3, lc = tid & 7;     // row 0..31, chunk 0..7
    const uint8_t* gB0 = (const uint8_t*)(g_wh + (size_t)(nb * BN + lr0) * KK + lc * 8);
    const uint32_t dB0 = swz8(lr0, lc);
    // j: +32 rows -> gmem +32*KK*2 bytes, smem +4096

    // ---- B ldmatrix bases (warp N=32 -> 2 ldm4 per k16) ----
    const int b_n = ((l >> 4) & 1) * 8 + (l & 7);
    const int b_cs = (l >> 3) & 1;
    uint32_t baseB[2];
#pragma unroll
    for (int nf2 = 0; nf2 < 2; nf2++)
        baseB[nf2] = swz8(nwarp * 32 + nf2 * 16 + b_n, b_cs);

    // ---- A direct-gmem addressing ----
    // lane owns rows {r0, r0+8} cols {2c,2c+1} (+8 in k) of each m16 frag
    const float* px = x + (size_t)(mb * BM + mwarp * 64 + (l >> 2)) * KK + 2 * (l & 3);
    // mf stride = 16*KK floats; +8 rows = 8*KK

    float acc[4][4][4];
#pragma unroll
    for (int i = 0; i < 4; i++)
#pragma unroll
        for (int j = 0; j < 4; j++)
#pragma unroll
            for (int k = 0; k < 4; k++) acc[i][j][k] = 0.0f;

    // prologue: B stages for kt 0,1
#pragma unroll
    for (int s = 0; s < 2; s++) {
        const uint32_t st = S + s * STAGE;
#pragma unroll
        for (int j = 0; j < 4; j++)
            CP16(st + dB0 + j * 4096, gB0 + (size_t)j * (32 * KK * 2) + s * 128);
        CP_COMMIT();
    }

    for (int kt = 0; kt < NKT; kt++) {
        CP_WAIT1();
        __syncthreads();
        if (kt + 2 < NKT) {
            const uint32_t st = S + ((kt + 2) % NSTAGE) * STAGE;
            const uint32_t go = (uint32_t)(kt + 2) * 128;
#pragma unroll
            for (int j = 0; j < 4; j++)
                CP16(st + dB0 + j * 4096, gB0 + (size_t)j * (32 * KK * 2) + go);
            CP_COMMIT();
        }
        const uint32_t stg = S + (kt % NSTAGE) * STAGE;
        const int kcol = kt * BK;

        uint32_t Bf[2][8];
#pragma unroll
        for (int nf2 = 0; nf2 < 2; nf2++)
            ldm4(&Bf[0][nf2 * 4], stg + baseB[nf2]);

#pragma unroll
        for (int ks = 0; ks < 4; ks++) {
            const int cur = ks & 1, nxt = cur ^ 1;
            if (ks < 3) {
                const uint32_t nko = (uint32_t)(2 * (ks + 1)) << 4;
#pragma unroll
                for (int nf2 = 0; nf2 < 2; nf2++)
                    ldm4(&Bf[nxt][nf2 * 4], stg + (baseB[nf2] ^ nko));
            }
            const int ko = kcol + ks * 16;

            // A half 1: mf 0,1  (8 LDG.64 batched, then cvt, then 8 MMAs)
#pragma unroll
            for (int h = 0; h < 2; h++) {
                float2 u[2][4];
#pragma unroll
                for (int m2 = 0; m2 < 2; m2++) {
                    const float* pr = px + (size_t)((h * 2 + m2) * 16) * KK + ko;
                    u[m2][0] = __ldg((const float2*)(pr));
                    u[m2][1] = __ldg((const float2*)(pr + 8));
                    u[m2][2] = __ldg((const float2*)(pr + 8 * KK));
                    u[m2][3] = __ldg((const float2*)(pr + 8 * KK + 8));
                }
#pragma unroll
                for (int m2 = 0; m2 < 2; m2++) {
                    uint32_t A[4];
                    A[0] = packh2(u[m2][0]);   // (r0,   k)
                    A[1] = packh2(u[m2][2]);   // (r0+8, k)
                    A[2] = packh2(u[m2][1]);   // (r0,   k+8)
                    A[3] = packh2(u[m2][3]);   // (r0+8, k+8)
#pragma unroll
                    for (int nf = 0; nf < 4; nf++)
                        mma_f16(acc[h * 2 + m2][nf], A, &Bf[cur][nf * 2]);
                }
            }
        }
    }

    // epilogue: bias + GELU
#pragma unroll
    for (int mf = 0; mf < 4; mf++) {
#pragma unroll
        for (int nf = 0; nf < 4; nf++) {
            int m0 = mb * BM + mwarp * 64 + mf * 16 + (l >> 2);
            int n0 = nb * BN + nwarp * 32 + nf * 8 + 2 * (l & 3);
            float b0 = __ldg(&bias[n0]);
            float b1 = __ldg(&bias[n0 + 1]);
            float2 v0, v1;
            v0.x = gelu_f(acc[mf][nf][0] + b0);
            v0.y = gelu_f(acc[mf][nf][1] + b1);
            v1.x = gelu_f(acc[mf][nf][2] + b0);
            v1.y = gelu_f(acc[mf][nf][3] + b1);
            *(float2*)&C[(size_t)m0 * OO + n0] = v0;
            *(float2*)&C[(size_t)(m0 + 8) * OO + n0] = v1;
        }
    }
}

// ---------------- launch ----------------
extern "C" void kernel_launch(void* const* d_in, const int* in_sizes, int n_in,
                              void* d_out, int out_size) {
    const float* x = (const float*)d_in[0];
    const float* W = (const float*)d_in[2];
    const float* b = (const float*)d_in[3];
    float* out = (float*)d_out;

    cudaFuncSetAttribute(gemm_f16_kernel,
                         cudaFuncAttributeMaxDynamicSharedMemorySize, SMEM_TOTAL);

    packw_kernel<<<(OO * KK / 8) / 256, 256>>>(W);   // 128 blocks, 0.5 MB

    dim3 grid(NN / BM, OO / BN);  // (64, 4) = 256 CTAs, 2/SM, single wave
    gemm_f16_kernel<<<grid, THREADS, SMEM_TOTAL>>>(x, b, out);
}

// round 13
// speedup vs baseline: 1.8323x; 1.8323x over previous
#include <cuda_runtime.h>
#include <cuda_fp16.h>
#include <cstdint>
#include <math.h>

// out = GELU_exact(x @ W.T + b)
// R13: fp16 single-term mma.sync GEMM (R11 structure) with FULL fragment
// software pipelining: both A and B ldmatrix fragments are double-buffered
// across k16 slices, so each slice's 16-MMA burst hides the next slice's
// LDSM latency. Tile 128x128, 8 warps (warp 64x32), occ 2, 3-stage cp.async.

#define NN 8192
#define KK 512
#define OO 512

#define BM 128
#define BN 128
#define BK 64                    // fp16 elems per k-tile (128 B/row)
#define NKT (KK / BK)            // 8
#define THREADS 256

#define ST_B   16384
#define STAGE  32768
#define NSTAGE 3
#define SMEM_TOTAL (NSTAGE * STAGE)   // 96 KB

__device__ __align__(128) __half g_xh[NN * KK];   // 8 MB
__device__ __align__(128) __half g_wh[OO * KK];   // 0.5 MB

__device__ __forceinline__ uint32_t smem_u32(const void* p) {
    uint32_t a;
    asm("{ .reg .u64 t; cvta.to.shared.u64 t, %1; cvt.u32.u64 %0, t; }" : "=r"(a) : "l"(p));
    return a;
}

#define CP16(dst, src) \
    asm volatile("cp.async.cg.shared.global [%0], [%1], 16;" :: "r"(dst), "l"(src) : "memory")
#define CP_COMMIT() asm volatile("cp.async.commit_group;" ::: "memory")
#define CP_WAIT1()  asm volatile("cp.async.wait_group 1;" ::: "memory")

__device__ __forceinline__ void ldm4(uint32_t* r, uint32_t addr) {
    asm volatile("ldmatrix.sync.aligned.m8n8.x4.shared.b16 {%0,%1,%2,%3}, [%4];"
                 : "=r"(r[0]), "=r"(r[1]), "=r"(r[2]), "=r"(r[3]) : "r"(addr));
}

__device__ __forceinline__ void mma_f16(float* d, const uint32_t* a, const uint32_t* b) {
    asm volatile(
        "mma.sync.aligned.m16n8k16.row.col.f32.f16.f16.f32 "
        "{%0,%1,%2,%3}, {%4,%5,%6,%7}, {%8,%9}, {%0,%1,%2,%3};"
        : "+f"(d[0]), "+f"(d[1]), "+f"(d[2]), "+f"(d[3])
        : "r"(a[0]), "r"(a[1]), "r"(a[2]), "r"(a[3]), "r"(b[0]), "r"(b[1]));
}

__device__ __forceinline__ uint32_t packh2(float2 u) {
    __half2 h = __float22half2_rn(u);
    return *(uint32_t*)&h;
}

// swizzled byte offset in a 128B-row tile: row r, 16B-chunk c (0..7)
__device__ __forceinline__ uint32_t swz8(int r, int c) {
    return (uint32_t)(r * 128 + (((c ^ (r & 7))) << 4));
}

// A&S 7.1.26 erf (abs err 1.5e-7)
__device__ __forceinline__ float gelu_f(float h) {
    float s = h * 0.70710678118654752f;
    float a = fabsf(s);
    float t = __frcp_rn(fmaf(0.3275911f, a, 1.0f));
    float p = fmaf(fmaf(fmaf(fmaf(1.061405429f, t, -1.453152027f), t, 1.421413741f),
                        t, -0.284496736f), t, 0.254829592f) * t;
    float e = __expf(-a * a);
    float erfv = fmaf(-p, e, 1.0f);
    erfv = copysignf(erfv, s);
    return 0.5f * h * (1.0f + erfv);
}

// ---------------- pack kernel: f32 -> fp16 (rne) ----------------
__global__ __launch_bounds__(256) void pack_kernel(const float* __restrict__ x,
                                                   const float* __restrict__ W) {
    const int g = blockIdx.x * 256 + threadIdx.x;
    const int A_GROUPS = NN * (KK / 8);
    const float* src;
    __half* dst;
    if (g < A_GROUPS) {
        src = x + (size_t)g * 8;
        dst = g_xh + (size_t)g * 8;
    } else {
        size_t g2 = (size_t)(g - A_GROUPS);
        src = W + g2 * 8;
        dst = g_wh + g2 * 8;
    }
    float4 v0 = *(const float4*)src;
    float4 v1 = *(const float4*)(src + 4);
    uint32_t o[4];
    o[0] = packh2(make_float2(v0.x, v0.y));
    o[1] = packh2(make_float2(v0.z, v0.w));
    o[2] = packh2(make_float2(v1.x, v1.y));
    o[3] = packh2(make_float2(v1.z, v1.w));
    *(uint4*)dst = make_uint4(o[0], o[1], o[2], o[3]);
}

// ---------------- main GEMM kernel ----------------
__global__ __launch_bounds__(THREADS, 2)
void gemm_f16_kernel(const float* __restrict__ bias, float* __restrict__ C) {
    extern __shared__ uint8_t smem[];
    const uint32_t S = smem_u32(smem);
    const int tid = threadIdx.x;
    const int l = tid & 31, wid = tid >> 5;
    const int mwarp = wid & 1;   // 2 M-warps of 64 rows
    const int nwarp = wid >> 1;  // 4 N-warps of 32 cols
    const int mb = blockIdx.x, nb = blockIdx.y;

    // ---- hoisted loader addressing ----
    const int lr = tid >> 3, lc = tid & 7;
    uint32_t s_dstA[4], s_dstB[4];
    const uint8_t *gA[4], *gB[4];
#pragma unroll
    for (int j = 0; j < 4; j++) {
        int r = lr + j * 32;
        s_dstA[j] = swz8(r, lc);
        s_dstB[j] = ST_B + swz8(r, lc);
        gA[j] = (const uint8_t*)(g_xh + (size_t)(mb * BM + r) * KK + lc * 8);
        gB[j] = (const uint8_t*)(g_wh + (size_t)(nb * BN + r) * KK + lc * 8);
    }

    // ---- hoisted ldmatrix bases (slice 0; slice ks = base ^ ((2*ks)<<4)) ----
    const int a_r = ((l >> 3) & 1) * 8 + (l & 7);
    const int a_cs = (l >> 4) & 1;
    const int b_n = ((l >> 4) & 1) * 8 + (l & 7);
    const int b_cs = (l >> 3) & 1;
    uint32_t baseA[4], baseB[2];
#pragma unroll
    for (int mf = 0; mf < 4; mf++) baseA[mf] = swz8(mwarp * 64 + mf * 16 + a_r, a_cs);
#pragma unroll
    for (int nf2 = 0; nf2 < 2; nf2++) baseB[nf2] = ST_B + swz8(nwarp * 32 + nf2 * 16 + b_n, b_cs);

    float acc[4][4][4];
#pragma unroll
    for (int i = 0; i < 4; i++)
#pragma unroll
        for (int j = 0; j < 4; j++)
#pragma unroll
            for (int k = 0; k < 4; k++) acc[i][j][k] = 0.0f;

    // prologue: stages for kt 0,1
#pragma unroll
    for (int s = 0; s < 2; s++) {
        const uint32_t st = S + s * STAGE;
#pragma unroll
        for (int j = 0; j < 4; j++) {
            CP16(st + s_dstA[j], gA[j] + s * 128);
            CP16(st + s_dstB[j], gB[j] + s * 128);
        }
        CP_COMMIT();
    }

    for (int kt = 0; kt < NKT; kt++) {
        CP_WAIT1();
        __syncthreads();
        if (kt + 2 < NKT) {
            const uint32_t st = S + ((kt + 2) % NSTAGE) * STAGE;
            const uint32_t go = (uint32_t)(kt + 2) * 128;
#pragma unroll
            for (int j = 0; j < 4; j++) {
                CP16(st + s_dstA[j], gA[j] + go);
                CP16(st + s_dstB[j], gB[j] + go);
            }
            CP_COMMIT();
        }
        const uint32_t stg = S + (kt % NSTAGE) * STAGE;

        // fragment double buffers: slice-level software pipeline
        uint32_t Af[2][4][4], Bf[2][8];
#pragma unroll
        for (int nf2 = 0; nf2 < 2; nf2++)
            ldm4(&Bf[0][nf2 * 4], stg + baseB[nf2]);
#pragma unroll
        for (int mf = 0; mf < 4; mf++)
            ldm4(Af[0][mf], stg + baseA[mf]);

#pragma unroll
        for (int ks = 0; ks < 4; ks++) {
            const int cur = ks & 1, nxt = cur ^ 1;
            if (ks < 3) {
                const uint32_t nko = (uint32_t)(2 * (ks + 1)) << 4;
#pragma unroll
                for (int nf2 = 0; nf2 < 2; nf2++)
                    ldm4(&Bf[nxt][nf2 * 4], stg + (baseB[nf2] ^ nko));
#pragma unroll
                for (int mf = 0; mf < 4; mf++)
                    ldm4(Af[nxt][mf], stg + (baseA[mf] ^ nko));
            }
            // 16 independent MMAs on current fragments (covers next LDSMs)
#pragma unroll
            for (int mf = 0; mf < 4; mf++)
#pragma unroll
                for (int nf = 0; nf < 4; nf++)
                    mma_f16(acc[mf][nf], Af[cur][mf], &Bf[cur][nf * 2]);
        }
    }

    // epilogue: bias + GELU
#pragma unroll
    for (int mf = 0; mf < 4; mf++) {
#pragma unroll
        for (int nf = 0; nf < 4; nf++) {
            int m0 = mb * BM + mwarp * 64 + mf * 16 + (l >> 2);
            int n0 = nb * BN + nwarp * 32 + nf * 8 + 2 * (l & 3);
            float b0 = __ldg(&bias[n0]);
            float b1 = __ldg(&bias[n0 + 1]);
            float2 v0, v1;
            v0.x = gelu_f(acc[mf][nf][0] + b0);
            v0.y = gelu_f(acc[mf][nf][1] + b1);
            v1.x = gelu_f(acc[mf][nf][2] + b0);
            v1.y = gelu_f(acc[mf][nf][3] + b1);
            *(float2*)&C[(size_t)m0 * OO + n0] = v0;
            *(float2*)&C[(size_t)(m0 + 8) * OO + n0] = v1;
        }
    }
}

// ---------------- launch ----------------
extern "C" void kernel_launch(void* const* d_in, const int* in_sizes, int n_in,
                              void* d_out, int out_size) {
    const float* x = (const float*)d_in[0];
    const float* W = (const float*)d_in[2];
    const float* b = (const float*)d_in[3];
    float* out = (float*)d_out;

    cudaFuncSetAttribute(gemm_f16_kernel,
                         cudaFuncAttributeMaxDynamicSharedMemorySize, SMEM_TOTAL);

    const int A_GROUPS = NN * (KK / 8);
    const int B_GROUPS = OO * (KK / 8);
    pack_kernel<<<(A_GROUPS + B_GROUPS) / 256, 256>>>(x, W);

    dim3 grid(NN / BM, OO / BN);  // (64, 4) = 256 CTAs, 2/SM, single wave
    gemm_f16_kernel<<<grid, THREADS, SMEM_TOTAL>>>(b, out);
}